// round 16
// baseline (speedup 1.0000x reference)
#include <cuda_runtime.h>
#include <cuda_bf16.h>
#include <stdint.h>
#include <math.h>
#include <string.h>

#define NB 16
#define NT 64
#define NV 32000
#define NE 256
#define NH 1024
#define NG 4096   // 4*H

// ---------------- device scratch (no allocs allowed) ----------------
__device__ float g_zx_enc[NB*NT*NG];
__device__ float g_zx_dec[NB*NT*NG];
__device__ float g_memory[NB*NT*NH];
__device__ float g_keys[NB*NT*NH];
__device__ float g_premem[NB*NT*NH];     // memory @ Wa2
__device__ float g_dec_out[NB*NT*NH];
__device__ float g_zpart[16*NB*NG];
__device__ float g_qapart[16*NB*2*NH];   // [q | h2@Wa1] K-split partials
__device__ float g_h[NB*NH];
__device__ float g_c[NB*NH];
__device__ float g_scores[NB*NT];
__device__ int   g_rowidx[NB*NT];
__device__ int   g_rowscat[NB*NT];
__device__ int   g_mpad;
// grid-barrier state (zero-initialized at module load; self-restoring)
__device__ unsigned g_arr;
__device__ unsigned g_gen;
// bf16 hi/lo split operands
__device__ __nv_bfloat16 g_Whi[(size_t)NH*NV];
__device__ __nv_bfloat16 g_Wlo[(size_t)NH*NV];
__device__ __nv_bfloat16 g_Ahi[(size_t)NB*NT*NH];
__device__ __nv_bfloat16 g_Alo[(size_t)NB*NT*NH];
// recurrent weights hi/lo: [enc 4M | dec 8M | qa 2M]
#define RW_ENC 0
#define RW_DEC (4*1024*1024)
#define RW_QA  (12*1024*1024)
__device__ __nv_bfloat16 g_RWhi[14*1024*1024];
__device__ __nv_bfloat16 g_RWlo[14*1024*1024];
// recurrent activations hi/lo
__device__ __nv_bfloat16 g_ye_hi[NB*NH],   g_ye_lo[NB*NH];     // encoder h
__device__ __nv_bfloat16 g_ya_hi[NB*2*NH], g_ya_lo[NB*2*NH];   // [attn | h]
__device__ __nv_bfloat16 g_yc_hi[NB*2*NH], g_yc_lo[NB*2*NH];   // [h2 | -]

__device__ __forceinline__ float sigm(float x){ return 1.f/(1.f + __expf(-x)); }
__device__ __forceinline__ float ftanh(float x){
  float a = fabsf(x);
  float e = __expf(-2.f * a);
  float t = (1.f - e) / (1.f + e);
  return copysignf(t, x);
}
__device__ __forceinline__ void bsplit(float v, __nv_bfloat16& h, __nv_bfloat16& l){
  h = __float2bfloat16_rn(v);
  l = __float2bfloat16_rn(v - __bfloat162float(h));
}

__device__ __forceinline__ unsigned smem_u32(const void* p){
  return (unsigned)__cvta_generic_to_shared(p);
}
__device__ __forceinline__ void cp16(unsigned dst, const void* src){
  asm volatile("cp.async.cg.shared.global [%0], [%1], 16;\n" :: "r"(dst), "l"(src));
}
__device__ __forceinline__ void cp4(unsigned dst, const void* src){
  asm volatile("cp.async.ca.shared.global [%0], [%1], 4;\n" :: "r"(dst), "l"(src));
}
__device__ __forceinline__ void cp_commit(){
  asm volatile("cp.async.commit_group;\n");
}
__device__ __forceinline__ void cp_wait0(){
  asm volatile("cp.async.wait_group 0;\n");
}

// software grid barrier: 128 co-resident blocks (grid must be exactly 128)
__device__ __forceinline__ void grid_sync(){
  __syncthreads();
  __threadfence();
  if (threadIdx.x == 0) {
    volatile unsigned* vg = &g_gen;
    unsigned g0 = *vg;
    if (atomicAdd(&g_arr, 1u) == 127u) {
      g_arr = 0u;
      __threadfence();
      atomicExch(&g_gen, g0 + 1u);
    } else {
      while (*vg == g0) { __nanosleep(64); }
    }
  }
  __syncthreads();
}

// ---------------- mma.sync helpers (R10/R11-proven) ----------------
__device__ __forceinline__ void ldm4(unsigned* r, unsigned a){
  asm volatile("ldmatrix.sync.aligned.m8n8.x4.shared.b16 {%0,%1,%2,%3}, [%4];"
    : "=r"(r[0]), "=r"(r[1]), "=r"(r[2]), "=r"(r[3]) : "r"(a));
}
__device__ __forceinline__ void ldm4t(unsigned* r, unsigned a){
  asm volatile("ldmatrix.sync.aligned.m8n8.x4.trans.shared.b16 {%0,%1,%2,%3}, [%4];"
    : "=r"(r[0]), "=r"(r[1]), "=r"(r[2]), "=r"(r[3]) : "r"(a));
}
__device__ __forceinline__ void mma_bf16(float* c, const unsigned* a,
                                         unsigned b0, unsigned b1){
  asm volatile(
    "mma.sync.aligned.m16n8k16.row.col.f32.bf16.bf16.f32 "
    "{%0,%1,%2,%3}, {%4,%5,%6,%7}, {%8,%9}, {%0,%1,%2,%3};"
    : "+f"(c[0]), "+f"(c[1]), "+f"(c[2]), "+f"(c[3])
    : "r"(a[0]), "r"(a[1]), "r"(a[2]), "r"(a[3]), "r"(b0), "r"(b1));
}
__device__ __forceinline__ unsigned pkbf2(__nv_bfloat16 a, __nv_bfloat16 b){
  __nv_bfloat162 t;
  t.x = a;
  t.y = b;
  unsigned u;
  memcpy(&u, &t, 4);
  return u;
}

// =====================================================================
// Shared skinny-MMA tile (M=16) — device function version of R11 kernel.
// y slab already staged in smem [16 rows x Kblk bf16] hi at 0, lo at
// 16*astride; B streamed double-buffered at 32*astride. Writes partials.
// =====================================================================
__device__ __forceinline__ void skinny_tile(
    unsigned sb, int Kblk,
    const __nv_bfloat16* __restrict__ Whi, const __nv_bfloat16* __restrict__ Wlo,
    int N, int kbase, int nblk, float* __restrict__ part, int prow)
{
  const int tid = threadIdx.x;
  const int lane = tid & 31;
  const int wid = tid >> 5;
  const int astride = Kblk*2 + 16;
  const unsigned yloOff = (unsigned)(16*astride);
  const unsigned bOff = 2u*yloOff;

#pragma unroll
  for (int rep = 0; rep < 2; rep++) {
    int i = tid + rep*256;
    int kr = i >> 4;
    int q = i & 15;
    unsigned dst = sb + bOff + (unsigned)(kr*272 + q*16);
    cp16(dst,        Whi + (size_t)(kbase+kr)*N + nblk + q*8);
    cp16(dst + 8704, Wlo + (size_t)(kbase+kr)*N + nblk + q*8);
  }
  cp_commit();

  float acc[2][4];
#pragma unroll
  for (int j = 0; j < 2; j++)
#pragma unroll
    for (int e = 0; e < 4; e++) acc[j][e] = 0.f;

  const int KT = Kblk >> 5;
  for (int kt = 0; kt < KT; kt++) {
    cp_wait0();
    __syncthreads();
    if (kt + 1 < KT) {
      int kc = kbase + (kt+1)*32;
      unsigned base = sb + bOff + (unsigned)(((kt+1) & 1) * 17408);
#pragma unroll
      for (int rep = 0; rep < 2; rep++) {
        int i = tid + rep*256;
        int kr = i >> 4;
        int q = i & 15;
        unsigned dst = base + (unsigned)(kr*272 + q*16);
        cp16(dst,        Whi + (size_t)(kc+kr)*N + nblk + q*8);
        cp16(dst + 8704, Wlo + (size_t)(kc+kr)*N + nblk + q*8);
      }
      cp_commit();
    }
    unsigned bB = sb + bOff + (unsigned)((kt & 1) * 17408);
#pragma unroll
    for (int ks2 = 0; ks2 < 2; ks2++) {
      unsigned aH[4], aL[4], bH[4], bL[4];
      int ar = lane & 15;
      int ak = (lane >> 4) * 8;
      unsigned ad = sb + (unsigned)(ar*astride + (kt*32 + ks2*16 + ak)*2);
      ldm4(aH, ad);
      ldm4(aL, ad + yloOff);
      int krow = ks2*16 + ((lane >> 3) & 1)*8 + (lane & 7);
      int nc = wid*16 + (lane >> 4)*8;
      unsigned bd = bB + (unsigned)(krow*272 + nc*2);
      ldm4t(bH, bd);
      ldm4t(bL, bd + 8704);
#pragma unroll
      for (int j = 0; j < 2; j++) {
        mma_bf16(acc[j], aH, bH[2*j], bH[2*j+1]);
        mma_bf16(acc[j], aH, bL[2*j], bL[2*j+1]);
        mma_bf16(acc[j], aL, bH[2*j], bH[2*j+1]);
      }
    }
  }

  int g = lane >> 2;
  int cn = (lane & 3) * 2;
#pragma unroll
  for (int j = 0; j < 2; j++) {
    int col = nblk + wid*16 + j*8 + cn;
    *(float2*)(part + (size_t)(prow + g) * N + col) =
        make_float2(acc[j][0], acc[j][1]);
    *(float2*)(part + (size_t)(prow + g + 8) * N + col) =
        make_float2(acc[j][2], acc[j][3]);
  }
}

// stage y slab into smem via L2 (__ldcg) — cross-SM safe inside persistent kernels
__device__ __forceinline__ void stage_y(
    char* sm, int Kblk,
    const __nv_bfloat16* __restrict__ yhi, const __nv_bfloat16* __restrict__ ylo,
    int ystride, int kbase)
{
  const int tid = threadIdx.x;
  const int astride = Kblk*2 + 16;
  const int yloOff = 16*astride;
  const int pairs = Kblk >> 1;
  for (int i = tid; i < 16*pairs; i += 256) {
    int b = i / pairs;
    int kp = i - b*pairs;
    const unsigned* ph = (const unsigned*)(yhi + (size_t)b*ystride + kbase) + kp;
    const unsigned* pl = (const unsigned*)(ylo + (size_t)b*ystride + kbase) + kp;
    *(unsigned*)(sm + b*astride + kp*4) = __ldcg(ph);
    *(unsigned*)(sm + yloOff + b*astride + kp*4) = __ldcg(pl);
  }
}

// =====================================================================
// Persistent ENCODER: 64 steps, 2 grid barriers/step. grid MUST be 128.
// smem = 16*528*2 + 2*17408 = 51712
// =====================================================================
__global__ __launch_bounds__(256, 1) void enc_persist(
    const int* __restrict__ enc_len,
    const __nv_bfloat16* __restrict__ Weh, const __nv_bfloat16* __restrict__ Wel)
{
  extern __shared__ __align__(128) char sm[];
  const unsigned sb = smem_u32(sm);
  const int tid = threadIdx.x;
  const int blk = blockIdx.x;

  for (int t = 0; t < NT; t++) {
    {  // z partials: N=4096, K=1024, 32 ntiles x 4 ksplits, Kblk=256
      int ntile = blk & 31;
      int ks = blk >> 5;
      stage_y(sm, 256, g_ye_hi, g_ye_lo, NH, ks*256);
      skinny_tile(sb, 256, Weh, Wel, NG, ks*256, ntile*128, g_zpart, ks*16);
    }
    grid_sync();
    if (tid < 128) {  // gates: 16384 elems, 128/block
      int idx = blk*128 + tid;
      int b = idx >> 10;
      int j = idx & 1023;
      size_t zo = (size_t)(b*NT + t) * NG + j;
      float zi = g_zx_enc[zo];
      float zj = g_zx_enc[zo+1024];
      float zf = g_zx_enc[zo+2048];
      float zoo = g_zx_enc[zo+3072];
#pragma unroll
      for (int s = 0; s < 4; s++) {
        size_t po = (size_t)(s*16 + b) * NG + j;
        zi  += __ldcg(&g_zpart[po]);
        zj  += __ldcg(&g_zpart[po+1024]);
        zf  += __ldcg(&g_zpart[po+2048]);
        zoo += __ldcg(&g_zpart[po+3072]);
      }
      float cn = g_c[idx] * sigm(zf + 1.f) + sigm(zi) * ftanh(zj);
      float hn = ftanh(cn) * sigm(zoo);
      bool valid = t < enc_len[b];
      if (valid) {
        g_h[idx] = hn;
        g_c[idx] = cn;
        bsplit(hn, g_ye_hi[idx], g_ye_lo[idx]);
      }
      g_memory[(size_t)(b*NT + t) * NH + j] = valid ? hn : 0.f;
    }
    grid_sync();
  }
}

// =====================================================================
// Persistent DECODER: 64 steps, 5 grid barriers/step. grid MUST be 128.
// smem = 16*1040*2 + 2*17408 = 68096
// =====================================================================
__global__ __launch_bounds__(256, 1) void dec_persist(
    const int* __restrict__ enc_len, const int* __restrict__ dec_len,
    const float* __restrict__ v_att,
    const __nv_bfloat16* __restrict__ Wdh, const __nv_bfloat16* __restrict__ Wdl,
    const __nv_bfloat16* __restrict__ Wqh, const __nv_bfloat16* __restrict__ Wql)
{
  extern __shared__ __align__(128) char sm[];
  const unsigned sb = smem_u32(sm);
  const int tid = threadIdx.x;
  const int lane = tid & 31;
  const int wid = tid >> 5;
  const int blk = blockIdx.x;
  float* smf = (float*)sm;

  for (int t = 0; t < NT; t++) {
    {  // z partials: N=4096, K=2048, 32 ntiles x 4 ksplits, Kblk=512
      int ntile = blk & 31;
      int ks = blk >> 5;
      stage_y(sm, 512, g_ya_hi, g_ya_lo, 2*NH, ks*512);
      skinny_tile(sb, 512, Wdh, Wdl, NG, ks*512, ntile*128, g_zpart, ks*16);
    }
    grid_sync();
    if (tid < 128) {  // gates
      int idx = blk*128 + tid;
      int b = idx >> 10;
      int j = idx & 1023;
      size_t zo = (size_t)(b*NT + t) * NG + j;
      float zi = g_zx_dec[zo];
      float zj = g_zx_dec[zo+1024];
      float zf = g_zx_dec[zo+2048];
      float zoo = g_zx_dec[zo+3072];
#pragma unroll
      for (int s = 0; s < 4; s++) {
        size_t po = (size_t)(s*16 + b) * NG + j;
        zi  += __ldcg(&g_zpart[po]);
        zj  += __ldcg(&g_zpart[po+1024]);
        zf  += __ldcg(&g_zpart[po+2048]);
        zoo += __ldcg(&g_zpart[po+3072]);
      }
      float cn = g_c[idx] * sigm(zf + 1.f) + sigm(zi) * ftanh(zj);
      float hn = ftanh(cn) * sigm(zoo);
      g_c[idx] = cn;
      __nv_bfloat16 hh, ll;
      bsplit(hn, hh, ll);
      g_ya_hi[b*2*NH + NH + j] = hh;
      g_ya_lo[b*2*NH + NH + j] = ll;
      g_yc_hi[b*2*NH + j] = hh;
      g_yc_lo[b*2*NH + j] = ll;
    }
    grid_sync();
    {  // qa partials: N=2048, K=1024, 16 ntiles x 8 ksplits, Kblk=128
      int ntile = blk & 15;
      int ks = blk >> 4;
      stage_y(sm, 128, g_yc_hi, g_yc_lo, 2*NH, ks*128);
      skinny_tile(sb, 128, Wqh, Wql, 2*NH, ks*128, ntile*128, g_qapart, ks*16);
    }
    grid_sync();
    {  // scores: b = blk>>3, tg = blk&7; sq at smf[0..1023], sv at smf[1024..]
      int b = blk >> 3;
      int tg = blk & 7;
      int L = enc_len[b];
      if (tg * 8 < L) {
        for (int hh = tid; hh < NH; hh += 256) {
          float qv = 0.f;
#pragma unroll
          for (int s = 0; s < 8; s++)
            qv += __ldcg(&g_qapart[(size_t)(s*16 + b) * 2*NH + hh]);
          smf[hh] = qv;
          smf[NH + hh] = v_att[hh];
        }
      }
      __syncthreads();
      int tt = tg * 8 + wid;
      if (tt < L) {
        const float* krow = g_keys + (size_t)(b*NT + tt) * NH;
        float acc = 0.f;
        for (int h0 = lane; h0 < NH; h0 += 32)
          acc += ftanh(krow[h0] + smf[h0]) * smf[NH + h0];
#pragma unroll
        for (int o = 16; o; o >>= 1) acc += __shfl_xor_sync(0xffffffffu, acc, o);
        if (lane == 0) g_scores[b*NT + tt] = acc;
      } else if (lane == 0) {
        g_scores[b*NT + tt] = -1e9f;
      }
    }
    grid_sync();
    {  // softmax + attn2: b = blk>>3, hc = blk&7; sal at smf[0..63]
      int b = blk >> 3;
      int hc = blk & 7;
      if (tid < NT) smf[tid] = __ldcg(&g_scores[b*NT + tid]);
      __syncthreads();
      float mx = -3e38f;
#pragma unroll
      for (int t2 = 0; t2 < NT; t2++) mx = fmaxf(mx, smf[t2]);
      __syncthreads();
      if (tid < NT) smf[tid] = __expf(smf[tid] - mx);
      __syncthreads();
      if (tid < 128) {
        float sum = 0.f;
#pragma unroll
        for (int t2 = 0; t2 < NT; t2++) sum += smf[t2];
        float inv = 1.f / sum;
        int j = hc * 128 + tid;
        float ha = 0.f;
#pragma unroll
        for (int s = 0; s < 8; s++)
          ha += __ldcg(&g_qapart[(size_t)(s*16 + b) * 2*NH + NH + j]);
        const float* pm = g_premem + (size_t)b * NT * NH + j;
        float cx = 0.f;
#pragma unroll 8
        for (int t2 = 0; t2 < NT; t2++) cx += smf[t2] * pm[(size_t)t2 * NH];
        float a = ha + cx * inv;
        bsplit(a, g_ya_hi[b*2*NH + j], g_ya_lo[b*2*NH + j]);
        g_dec_out[(size_t)(b*NT + t) * NH + j] = (t >= dec_len[b]) ? 0.f : a;
      }
    }
    grid_sync();
  }
}

// =====================================================================
// fp32 -> (hi, lo) bf16 splits
// =====================================================================
__global__ void conv_split(const float* __restrict__ src,
                           __nv_bfloat16* __restrict__ hi,
                           __nv_bfloat16* __restrict__ lo)
{
  size_t i = ((size_t)blockIdx.x * 256 + threadIdx.x) * 4;
  float4 v = *(const float4*)(src + i);
  __nv_bfloat16 h0, h1, h2, h3, l0, l1, l2, l3;
  bsplit(v.x, h0, l0);
  bsplit(v.y, h1, l1);
  bsplit(v.z, h2, l2);
  bsplit(v.w, h3, l3);
  *(uint2*)(hi + i) = make_uint2(pkbf2(h0, h1), pkbf2(h2, h3));
  *(uint2*)(lo + i) = make_uint2(pkbf2(l0, l1), pkbf2(l2, l3));
}

__global__ void conv_qa(const float* __restrict__ Wq, const float* __restrict__ Wa)
{
  size_t i = ((size_t)blockIdx.x * 256 + threadIdx.x) * 4;
  int k = (int)(i >> 11);
  int col = (int)(i & 2047);
  const float* src = (col < 1024) ? (Wq + (size_t)k * NH + col)
                                  : (Wa + (size_t)k * NH + (col - 1024));
  float4 v = *(const float4*)src;
  __nv_bfloat16 h0, h1, h2, h3, l0, l1, l2, l3;
  bsplit(v.x, h0, l0);
  bsplit(v.y, h1, l1);
  bsplit(v.z, h2, l2);
  bsplit(v.w, h3, l3);
  *(uint2*)(g_RWhi + RW_QA + i) = make_uint2(pkbf2(h0, h1), pkbf2(h2, h3));
  *(uint2*)(g_RWlo + RW_QA + i) = make_uint2(pkbf2(l0, l1), pkbf2(l2, l3));
}

__global__ void conv_A()
{
  size_t i = ((size_t)blockIdx.x * 256 + threadIdx.x) * 4;
  int row = (int)(i >> 10);
  int k = (int)(i & 1023);
  int src = g_rowidx[row];
  float4 v = *(const float4*)(g_dec_out + (size_t)src * NH + k);
  __nv_bfloat16 h0, h1, h2, h3, l0, l1, l2, l3;
  bsplit(v.x, h0, l0);
  bsplit(v.y, h1, l1);
  bsplit(v.z, h2, l2);
  bsplit(v.w, h3, l3);
  *(uint2*)(g_Ahi + i) = make_uint2(pkbf2(h0, h1), pkbf2(h2, h3));
  *(uint2*)(g_Alo + i) = make_uint2(pkbf2(l0, l1), pkbf2(l2, l3));
}

// =====================================================================
// Logits GEMM via mma.sync (R10-proven)
// =====================================================================
__global__ __launch_bounds__(256, 2) void logits_mma(
    const __nv_bfloat16* __restrict__ Ahi, const __nv_bfloat16* __restrict__ Alo,
    const __nv_bfloat16* __restrict__ Whi, const __nv_bfloat16* __restrict__ Wlo,
    float* __restrict__ C, const int* __restrict__ rowC,
    const int* __restrict__ mlimit)
{
  extern __shared__ __align__(128) char sm[];
  const int mbase = blockIdx.y * 128;
  if (mbase >= *mlimit) return;
  const int n0 = blockIdx.x * 64;

  const unsigned sb = smem_u32(sm);
  const int tid = threadIdx.x;
  const int lane = tid & 31;
  const int wid = tid >> 5;
  const int wm = wid & 3;
  const int wn = wid >> 2;

  float acc[2][4][4];
#pragma unroll
  for (int mt = 0; mt < 2; mt++)
#pragma unroll
    for (int nt = 0; nt < 4; nt++)
#pragma unroll
      for (int e = 0; e < 4; e++) acc[mt][nt][e] = 0.f;

#pragma unroll
  for (int rep = 0; rep < 2; rep++) {
    int i = tid + rep * 256;
    int m = i >> 2;
    int q = i & 3;
    unsigned dst = sb + m*80 + q*16;
    cp16(dst,         Ahi + (size_t)(mbase + m) * NH + q*8);
    cp16(dst + 10240, Alo + (size_t)(mbase + m) * NH + q*8);
  }
  {
    int kr = tid >> 3;
    int q = tid & 7;
    unsigned dst = sb + 40960 + kr*144 + q*16;
    cp16(dst,        Whi + (size_t)kr * NV + n0 + q*8);
    cp16(dst + 4608, Wlo + (size_t)kr * NV + n0 + q*8);
  }
  cp_commit();

  for (int kt = 0; kt < 32; kt++) {
    cp_wait0();
    __syncthreads();
    if (kt + 1 < 32) {
      const int kc = (kt + 1) * 32;
      const int nb = (kt + 1) & 1;
#pragma unroll
      for (int rep = 0; rep < 2; rep++) {
        int i = tid + rep * 256;
        int m = i >> 2;
        int q = i & 3;
        unsigned dst = sb + nb*20480 + m*80 + q*16;
        cp16(dst,         Ahi + (size_t)(mbase + m) * NH + kc + q*8);
        cp16(dst + 10240, Alo + (size_t)(mbase + m) * NH + kc + q*8);
      }
      {
        int kr = tid >> 3;
        int q = tid & 7;
        unsigned dst = sb + 40960 + nb*9216 + kr*144 + q*16;
        cp16(dst,        Whi + (size_t)(kc + kr) * NV + n0 + q*8);
        cp16(dst + 4608, Wlo + (size_t)(kc + kr) * NV + n0 + q*8);
      }
      cp_commit();
    }

    const int buf = kt & 1;
    const unsigned aB = sb + buf*20480;
    const unsigned bB = sb + 40960 + buf*9216;

#pragma unroll
    for (int ks = 0; ks < 2; ks++) {
      unsigned aH[2][4], aL[2][4], bH[2][4], bL[2][4];
      const int ar = lane & 15;
      const int ak = (lane >> 4) * 8;
#pragma unroll
      for (int mt = 0; mt < 2; mt++) {
        unsigned ad = aB + (unsigned)((wm*32 + mt*16 + ar)*80 + (ks*16 + ak)*2);
        ldm4(aH[mt], ad);
        ldm4(aL[mt], ad + 10240);
      }
      const int krow = ks*16 + ((lane >> 3) & 1)*8 + (lane & 7);
#pragma unroll
      for (int p = 0; p < 2; p++) {
        int nc = wn*32 + p*16 + (lane >> 4)*8;
        unsigned bd = bB + (unsigned)(krow*144 + nc*2);
        ldm4t(bH[p], bd);
        ldm4t(bL[p], bd + 4608);
      }
#pragma unroll
      for (int mt = 0; mt < 2; mt++)
#pragma unroll
        for (int p = 0; p < 2; p++)
#pragma unroll
          for (int j = 0; j < 2; j++) {
            int nt = p*2 + j;
            mma_bf16(acc[mt][nt], aH[mt], bH[p][2*j], bH[p][2*j+1]);
            mma_bf16(acc[mt][nt], aH[mt], bL[p][2*j], bL[p][2*j+1]);
            mma_bf16(acc[mt][nt], aL[mt], bH[p][2*j], bH[p][2*j+1]);
          }
    }
  }

  const int g = lane >> 2;
  const int c0n = (lane & 3) * 2;
#pragma unroll
  for (int mt = 0; mt < 2; mt++) {
    int r0 = wm*32 + mt*16 + g;
    int sc0 = rowC[mbase + r0];
    int sc1 = rowC[mbase + r0 + 8];
#pragma unroll
    for (int nt = 0; nt < 4; nt++) {
      int col = n0 + wn*32 + nt*8 + c0n;
      if (sc0 >= 0)
        *(float2*)(C + (size_t)sc0 * NV + col) = make_float2(acc[mt][nt][0], acc[mt][nt][1]);
      if (sc1 >= 0)
        *(float2*)(C + (size_t)sc1 * NV + col) = make_float2(acc[mt][nt][2], acc[mt][nt][3]);
    }
  }
}

// =====================================================================
// cp.async double-buffered SGEMM (R7-proven)
// =====================================================================
__global__ __launch_bounds__(256, 2) void sgemm_db(
    int M, int N, int K,
    const float* __restrict__ A, const float* __restrict__ W,
    const float* __restrict__ bias, float* __restrict__ C,
    const int* __restrict__ rowA, const int* __restrict__ rowC,
    const int* __restrict__ mlimit)
{
  __shared__ float As[2][8][128];
  __shared__ float Bs[2][8][128];
  const int mbase = blockIdx.y * 128;
  if (mlimit && mbase >= *mlimit) return;
  const int nbase = blockIdx.x * 128;
  const int tid = threadIdx.x;
  const int tx = tid & 15;
  const int ty = tid >> 4;
  const int arow = tid >> 1;
  const int acol = (tid & 1) << 2;
  const int brow = tid >> 5;
  const int bcol = (tid & 31) << 2;
  int aIdx = mbase + arow;
  if (rowA) aIdx = rowA[aIdx];
  const float* Ap = A + (size_t)aIdx * K + acol;
  const float* Wp = W + (size_t)brow * N + nbase + bcol;

  unsigned sA[2][4];
  unsigned sB[2];
#pragma unroll
  for (int bf = 0; bf < 2; bf++) {
#pragma unroll
    for (int qq = 0; qq < 4; qq++) sA[bf][qq] = smem_u32(&As[bf][acol + qq][arow]);
    sB[bf] = smem_u32(&Bs[bf][brow][bcol]);
  }

  float acc[8][8];
#pragma unroll
  for (int i = 0; i < 8; i++)
#pragma unroll
    for (int j = 0; j < 8; j++) acc[i][j] = 0.f;

  const int KT = K >> 3;
#pragma unroll
  for (int qq = 0; qq < 4; qq++) cp4(sA[0][qq], Ap + qq);
  cp16(sB[0], Wp);
  cp_commit();

  for (int kt = 0; kt < KT; kt++) {
    cp_wait0();
    __syncthreads();
    if (kt + 1 < KT) {
      const float* Ap2 = Ap + (kt + 1) * 8;
      const float* Wp2 = Wp + (size_t)(kt + 1) * 8 * N;
      int nb = (kt + 1) & 1;
#pragma unroll
      for (int qq = 0; qq < 4; qq++) cp4(sA[nb][qq], Ap2 + qq);
      cp16(sB[nb], Wp2);
      cp_commit();
    }
    int cb = kt & 1;
#pragma unroll
    for (int kk = 0; kk < 8; kk++) {
      float ar[8];
      float br[8];
#pragma unroll
      for (int i = 0; i < 8; i++) ar[i] = As[cb][kk][ty*8 + i];
#pragma unroll
      for (int j = 0; j < 8; j++) br[j] = Bs[cb][kk][tx*8 + j];
#pragma unroll
      for (int i = 0; i < 8; i++)
#pragma unroll
        for (int j = 0; j < 8; j++) acc[i][j] += ar[i] * br[j];
    }
  }

  float bvals[8];
#pragma unroll
  for (int j = 0; j < 8; j++) bvals[j] = bias ? bias[nbase + tx*8 + j] : 0.f;
#pragma unroll
  for (int i = 0; i < 8; i++) {
    int crow = mbase + ty*8 + i;
    int cIdx = rowC ? rowC[crow] : crow;
    if (cIdx < 0) continue;
    float* cp = C + (size_t)cIdx * N + nbase + tx*8;
    float4 o0 = make_float4(acc[i][0]+bvals[0], acc[i][1]+bvals[1],
                            acc[i][2]+bvals[2], acc[i][3]+bvals[3]);
    float4 o1 = make_float4(acc[i][4]+bvals[4], acc[i][5]+bvals[5],
                            acc[i][6]+bvals[6], acc[i][7]+bvals[7]);
    *(float4*)(cp)     = o0;
    *(float4*)(cp + 4) = o1;
  }
}

// =====================================================================
// Small kernels
// =====================================================================
__global__ void zero_state()
{
  int idx = blockIdx.x * 256 + threadIdx.x;
  g_h[idx] = 0.f;
  g_c[idx] = 0.f;
  g_ye_hi[idx] = __float2bfloat16(0.f);
  g_ye_lo[idx] = __float2bfloat16(0.f);
}

__global__ void build_rowlist(const int* __restrict__ dec_len)
{
  __shared__ int off[17];
  if (threadIdx.x == 0) {
    int s = 0;
    off[0] = 0;
    for (int b = 0; b < NB; b++) {
      s += dec_len[b];
      off[b+1] = s;
    }
    g_mpad = (s + 127) & ~127;
  }
  __syncthreads();
  int nv = off[16];
  int mpad = (nv + 127) & ~127;
  for (int i = threadIdx.x; i < NB*NT; i += 256) {
    if (i < nv) {
      int b = 0;
      while (off[b+1] <= i) b++;
      int r = b*NT + (i - off[b]);
      g_rowidx[i] = r;
      g_rowscat[i] = r;
    } else if (i < mpad) {
      g_rowidx[i] = 0;
      g_rowscat[i] = -1;
    }
  }
}

__global__ void zero_invalid_logits(const int* __restrict__ dec_len, float* __restrict__ out)
{
  int row = blockIdx.y;
  int b = row >> 6;
  int t = row & 63;
  if (t < dec_len[b]) return;
  int c = (blockIdx.x * 256 + threadIdx.x) * 4;
  if (c < NV) {
    *(float4*)(out + (size_t)row * NV + c) = make_float4(0.f, 0.f, 0.f, 0.f);
  }
}

__global__ void dec_init()
{
  int idx = blockIdx.x * 256 + threadIdx.x;
  int b = idx >> 11;
  int j = idx & 2047;
  float v = (j < 1024) ? 0.f : g_h[b*NH + (j - 1024)];
  bsplit(v, g_ya_hi[idx], g_ya_lo[idx]);
}

// =====================================================================
// Host launch
// =====================================================================
extern "C" void kernel_launch(void* const* d_in, const int* in_sizes, int n_in,
                              void* d_out, int out_size)
{
  const int*   enc_in      = (const int*)d_in[0];
  const int*   dec_in      = (const int*)d_in[1];
  const int*   enc_len     = (const int*)d_in[2];
  const int*   dec_len     = (const int*)d_in[3];
  const float* embedding   = (const float*)d_in[4];
  const float* enc_kernel  = (const float*)d_in[5];
  const float* enc_bias    = (const float*)d_in[6];
  const float* dec_kernel  = (const float*)d_in[7];
  const float* dec_bias    = (const float*)d_in[8];
  const float* Wm          = (const float*)d_in[9];
  const float* Wq          = (const float*)d_in[10];
  const float* v_att       = (const float*)d_in[11];
  const float* attn_kernel = (const float*)d_in[12];
  const float* out_kernel  = (const float*)d_in[13];
  float* out = (float*)d_out;
  (void)in_sizes;
  (void)n_in;
  (void)out_size;

  float *zx_enc, *zx_dec, *mem, *keys, *premem;
  int *rowscat, *mpad;
  __nv_bfloat16 *whi, *wlo, *ahi, *alo, *rwhi, *rwlo;
  cudaGetSymbolAddress((void**)&zx_enc, g_zx_enc);
  cudaGetSymbolAddress((void**)&zx_dec, g_zx_dec);
  cudaGetSymbolAddress((void**)&mem,    g_memory);
  cudaGetSymbolAddress((void**)&keys,   g_keys);
  cudaGetSymbolAddress((void**)&premem, g_premem);
  cudaGetSymbolAddress((void**)&rowscat, g_rowscat);
  cudaGetSymbolAddress((void**)&mpad,   g_mpad);
  cudaGetSymbolAddress((void**)&whi,    g_Whi);
  cudaGetSymbolAddress((void**)&wlo,    g_Wlo);
  cudaGetSymbolAddress((void**)&ahi,    g_Ahi);
  cudaGetSymbolAddress((void**)&alo,    g_Alo);
  cudaGetSymbolAddress((void**)&rwhi,   g_RWhi);
  cudaGetSymbolAddress((void**)&rwlo,   g_RWlo);

  const int LOGITS_SMEM = 2*2*10240 + 2*2*4608;  // 59392
  const int ENC_SMEM = 16*528*2 + 2*17408;       // 51712
  const int DEC_SMEM = 16*1040*2 + 2*17408;      // 68096
  cudaFuncSetAttribute(logits_mma, cudaFuncAttributeMaxDynamicSharedMemorySize,
                       LOGITS_SMEM);
  cudaFuncSetAttribute(enc_persist, cudaFuncAttributeMaxDynamicSharedMemorySize,
                       ENC_SMEM);
  cudaFuncSetAttribute(dec_persist, cudaFuncAttributeMaxDynamicSharedMemorySize,
                       DEC_SMEM);

  zero_state<<<64, 256>>>();
  build_rowlist<<<1, 256>>>(dec_len);
  zero_invalid_logits<<<dim3(32, 1024), 256>>>(dec_len, out);

  // fp32 -> bf16 hi/lo weight splits (once)
  conv_split<<<NV, 256>>>(out_kernel, whi, wlo);
  conv_split<<<4096, 256>>>(enc_kernel + (size_t)NE*NG, rwhi + RW_ENC, rwlo + RW_ENC);
  conv_split<<<8192, 256>>>(dec_kernel + (size_t)NE*NG, rwhi + RW_DEC, rwlo + RW_DEC);
  conv_qa<<<2048, 256>>>(Wq, attn_kernel);

  // Zx precompute: emb-gather GEMMs [1024 x 4096 x 256] with bias
  sgemm_db<<<dim3(32, 8), 256>>>(NB*NT, NG, NE, embedding, enc_kernel, enc_bias,
                                 zx_enc, enc_in, nullptr, nullptr);
  sgemm_db<<<dim3(32, 8), 256>>>(NB*NT, NG, NE, embedding, dec_kernel, dec_bias,
                                 zx_dec, dec_in, nullptr, nullptr);

  // ---- encoder: one persistent kernel (64 steps) ----
  enc_persist<<<128, 256, ENC_SMEM>>>(enc_len, rwhi + RW_ENC, rwlo + RW_ENC);

  // keys = memory @ Wm ; premem = memory @ Wa2
  sgemm_db<<<dim3(8, 8), 256>>>(NB*NT, NH, NH, mem, Wm, nullptr, keys,
                                nullptr, nullptr, nullptr);
  sgemm_db<<<dim3(8, 8), 256>>>(NB*NT, NH, NH, mem, attn_kernel + (size_t)NH*NH,
                                nullptr, premem, nullptr, nullptr, nullptr);

  // ---- decoder: one persistent kernel (64 steps) ----
  dec_init<<<128, 256>>>();
  dec_persist<<<128, 256, DEC_SMEM>>>(enc_len, dec_len, v_att,
                                      rwhi + RW_DEC, rwlo + RW_DEC,
                                      rwhi + RW_QA, rwlo + RW_QA);

  // compact + split dec_out rows, then tensor-core logits GEMM
  conv_A<<<1024, 256>>>();
  logits_mma<<<dim3(500, 8), 256, LOGITS_SMEM>>>(ahi, alo, whi, wlo, out,
                                                 rowscat, mpad);
}